// round 11
// baseline (speedup 1.0000x reference)
#include <cuda_runtime.h>
#include <cuda_bf16.h>
#include <math.h>
#include <stdint.h>

#define BB 256
#define LL 256
#define VV 14
#define EMBD 512
#define HH 128
#define OC 256
#define NP 196
#define NPP 256
#define KLIN 32768
#define NJ 128
#define SPLITK 64
#define KC (KLIN/SPLITK)   // 512 -> 4 conv channels per CTA

typedef unsigned long long ull;

// dynamic smem layout for k_gemmW (bytes)
#define PLSTRIDE 18432     // 128 rows x 144B (72 bf16, padded)
#define A_OFF    0         // 3 planes
#define B_OFF    55296     // 3 planes
#define P2_OFF   110592    // 3072 fp32 = 12288
#define SPI_OFF  122880    // 128 x 132 uchar = 16896
#define BIAS_OFF 139776    // 16
#define W_TOTAL  139792

__device__ float g_poolT_e[EMBD*NPP];
__device__ float g_poolT_f[EMBD*NPP];
__device__ float g_pbpart[4*2*3*OC*NPP];
__device__ float g_P2[2*3*OC*NPP];
__device__ unsigned char g_pi8T[2*HH*BB];
__device__ uint16_t g_Wbf[(size_t)2*3*128*KLIN];   // [br][plane][j][k] bf16 bits
__device__ float g_partial[SPLITK*BB*NJ];
__device__ float g_vec[BB*NJ];
__device__ float g_r[3*BB*64];
__device__ float g_Wsum[3*64*128];
__device__ float g_Lmid[64*256];
__device__ int   g_tok[BB*256];

__device__ __forceinline__ ull pk2(float lo, float hi){
    ull r; asm("mov.b64 %0, {%1, %2};" : "=l"(r) : "f"(lo), "f"(hi)); return r;
}
__device__ __forceinline__ void ffma2(ull& c, ull a, ull b){
    asm("fma.rn.f32x2 %0, %1, %2, %0;" : "+l"(c) : "l"(a), "l"(b));
}
__device__ __forceinline__ uint32_t smem_u32(const void* p){
    uint32_t a;
    asm("{ .reg .u64 t; cvta.to.shared.u64 t, %1; cvt.u32.u64 %0, t; }" : "=r"(a) : "l"(p));
    return a;
}
__device__ __forceinline__ void ldm4(uint32_t* r, uint32_t addr){
    asm volatile("ldmatrix.sync.aligned.m8n8.x4.shared.b16 {%0,%1,%2,%3}, [%4];"
        : "=r"(r[0]), "=r"(r[1]), "=r"(r[2]), "=r"(r[3]) : "r"(addr));
}
__device__ __forceinline__ void mma16816(float* c, const uint32_t* a, uint32_t b0, uint32_t b1){
    asm volatile("mma.sync.aligned.m16n8k16.row.col.f32.bf16.bf16.f32 "
        "{%0,%1,%2,%3}, {%4,%5,%6,%7}, {%8,%9}, {%0,%1,%2,%3};"
        : "+f"(c[0]), "+f"(c[1]), "+f"(c[2]), "+f"(c[3])
        : "r"(a[0]), "r"(a[1]), "r"(a[2]), "r"(a[3]), "r"(b0), "r"(b1));
}
__device__ __forceinline__ void bsplit(float v, uint16_t& h, uint16_t& m, uint16_t& l){
    __nv_bfloat16 b0 = __float2bfloat16_rn(v);
    float r1 = v - __bfloat162float(b0);
    __nv_bfloat16 b1 = __float2bfloat16_rn(r1);
    float r2 = r1 - __bfloat162float(b1);
    __nv_bfloat16 b2 = __float2bfloat16_rn(r2);
    h = __bfloat16_as_ushort(b0); m = __bfloat16_as_ushort(b1); l = __bfloat16_as_ushort(b2);
}

__global__ void k_poolT2(const float* __restrict__ eemb, const float* __restrict__ femb){
    int idx = blockIdx.x*256 + threadIdx.x;
    int br = idx / (EMBD*NPP), r = idx % (EMBD*NPP);
    int c = r >> 8, p = r & 255;
    const float* emb = br ? femb : eemb;
    float v = 0.f;
    if (p < NP){
        int t1 = p / VV, t2 = p % VV;
        v = fmaxf(emb[t1*EMBD + c], emb[t2*EMBD + c]);
    }
    (br ? g_poolT_f : g_poolT_e)[c*NPP + p] = v;
}

__global__ __launch_bounds__(512) void k_pbuild2(const float* __restrict__ ecw,
                                                 const float* __restrict__ fcw){
    int ot = blockIdx.x, cs = blockIdx.y, br = blockIdx.z;
    const float* cw    = br ? fcw : ecw;
    const float* poolT = br ? g_poolT_f : g_poolT_e;
    int o0 = ot*8, c0 = cs*128;
    __shared__ float ws[8*3*128];
    int tid = threadIdx.x;
    for (int e = tid; e < 3072; e += 512){
        int oi = e / 384, r = e % 384, kh = r >> 7, c = r & 127;
        ws[e] = cw[((size_t)(o0+oi)*EMBD + (c0+c))*9 + 1 + kh*3];
    }
    __syncthreads();
    int pg = tid & 63, oi = tid >> 6, p0 = pg*4;
    ull a0=0,a1=0,a2=0,a3=0,a4=0,a5=0;
    const float* pt  = poolT + (size_t)c0*NPP + p0;
    const float* wsp = ws + oi*384;
    #pragma unroll 4
    for (int c = 0; c < 128; c++){
        float4 pv = *(const float4*)(pt + (size_t)c*NPP);
        ull pa0 = pk2(pv.x, pv.y), pa1 = pk2(pv.z, pv.w);
        float w0 = wsp[c], w1 = wsp[128+c], w2 = wsp[256+c];
        ull b0 = pk2(w0,w0), b1 = pk2(w1,w1), b2 = pk2(w2,w2);
        ffma2(a0, pa0, b0); ffma2(a1, pa1, b0);
        ffma2(a2, pa0, b1); ffma2(a3, pa1, b1);
        ffma2(a4, pa0, b2); ffma2(a5, pa1, b2);
    }
    size_t base = (((size_t)(cs*2 + br)*3)*OC + (o0+oi))*NPP + p0;
    *(ulonglong2*)(g_pbpart + base)            = make_ulonglong2(a0, a1);
    *(ulonglong2*)(g_pbpart + base + OC*NPP)   = make_ulonglong2(a2, a3);
    *(ulonglong2*)(g_pbpart + base + 2*OC*NPP) = make_ulonglong2(a4, a5);
}

__global__ void k_pbreduce(){
    int idx = blockIdx.x*256 + threadIdx.x;
    int br = idx / (3*OC*NPP), inner = idx % (3*OC*NPP);
    float s = g_pbpart[(0*2+br)*(3*OC*NPP) + inner]
            + g_pbpart[(1*2+br)*(3*OC*NPP) + inner]
            + g_pbpart[(2*2+br)*(3*OC*NPP) + inner]
            + g_pbpart[(3*2+br)*(3*OC*NPP) + inner];
    g_P2[idx] = s;
}

__global__ void k_pairidx8(int which, const int* __restrict__ x){
    int idx = blockIdx.x*256 + threadIdx.x;
    int b = idx & 255, h = idx >> 8;
    const int* tok = which ? g_tok : x;
    g_pi8T[which*HH*BB + idx] =
        (unsigned char)(tok[b*LL + 2*h]*VV + tok[b*LL + 2*h + 1]);
}

// ---- W pre-split: fp32 [k][j] -> 3 bf16 planes transposed [j][k] -----------
__global__ void k_wsplit(const float* __restrict__ elw, const float* __restrict__ flw1){
    // grid (1024, 4, 2), block 256: tile 32k x 32j
    int k0 = blockIdx.x*32, j0 = blockIdx.y*32, br = blockIdx.z;
    const float* W = br ? flw1 : elw;
    __shared__ uint16_t sh[3][32][33];
    int tid = threadIdx.x;
    int jl = tid & 31, kl = tid >> 5;
    #pragma unroll
    for (int p = 0; p < 4; p++){
        int k = kl + p*8;
        float v = W[(size_t)(k0+k)*NJ + j0 + jl];
        uint16_t h,m,l; bsplit(v,h,m,l);
        sh[0][k][jl]=h; sh[1][k][jl]=m; sh[2][k][jl]=l;
    }
    __syncthreads();
    int kl2 = tid & 31, jl2 = tid >> 5;
    size_t base = (size_t)br*3*128*KLIN;
    #pragma unroll
    for (int p = 0; p < 4; p++){
        int j = jl2 + p*8;
        #pragma unroll
        for (int pl = 0; pl < 3; pl++)
            g_Wbf[base + ((size_t)pl*128 + j0 + j)*KLIN + k0 + kl2] = sh[pl][kl2][j];
    }
}

// ---- warp-MMA fused conv+GEMM v2: interleaved mma, pre-split B -------------
__global__ __launch_bounds__(256) void k_gemmW(int which, const float* __restrict__ bias){
    extern __shared__ char dyn[];
    const int tid = threadIdx.x;
    const int wid = tid >> 5, lane = tid & 31;
    const int m0 = blockIdx.x * 128;
    const int kz = blockIdx.y;
    const int k0 = kz * KC;
    const int oF = k0 >> 7;
    const uint32_t sbase = smem_u32(dyn);

    float* sP2   = (float*)(dyn + P2_OFF);
    unsigned char (*spi)[132] = (unsigned char(*)[132])(dyn + SPI_OFF);
    float* sbias = (float*)(dyn + BIAS_OFF);

    const float* P2 = g_P2 + (size_t)which*(3*OC*NPP);
    for (int e = tid; e < 3072; e += 256){
        int oi = e / 768, r = e % 768;
        sP2[e] = P2[(size_t)(r >> 8)*OC*NPP + (oF + oi)*NPP + (r & 255)];
    }
    const unsigned char* piT = g_pi8T + (size_t)which*(HH*BB);
    for (int e = tid; e < 4096; e += 256){
        int h = e >> 5, g = e & 31;
        *(uchar4*)&spi[h][g*4] = *(const uchar4*)(piT + h*BB + m0 + g*4);
    }
    if (tid < 4) sbias[tid] = bias[oF + tid];
    __syncthreads();

    const int mBase = (wid >> 1) * 32;
    const int nBase = (wid & 1) * 64;
    float acc[2][8][4];
    #pragma unroll
    for (int i=0;i<2;i++)
        #pragma unroll
        for (int j=0;j<8;j++)
            #pragma unroll
            for (int q=0;q<4;q++) acc[i][j][q] = 0.f;

    const int rowT = tid & 127;
    const int khT  = tid >> 7;

    for (int t = 0; t < 8; t++){
        int kt = k0 + t*64;
        // A build: conv from LUT -> 3 bf16 planes [m][72]
        {
            int oi = t >> 1, h0 = (t & 1) * 64;
            const float* pa = sP2 + oi*768;
            float vb = sbias[oi];
            char* baseA = dyn + A_OFF + rowT*144 + khT*64;
            #pragma unroll 4
            for (int ip = 0; ip < 16; ip++){
                uint16_t h0a,m0a,l0a,h1a,m1a,l1a;
                #pragma unroll
                for (int e2 = 0; e2 < 2; e2++){
                    int h = h0 + khT*32 + ip*2 + e2;
                    float v = vb;
                    if (h > 0)   v += pa[(int)spi[h-1][rowT]];
                    v += pa[256 + (int)spi[h][rowT]];
                    if (h < 127) v += pa[512 + (int)spi[h+1][rowT]];
                    if (e2){ bsplit(v, h1a, m1a, l1a); } else { bsplit(v, h0a, m0a, l0a); }
                }
                *(uint32_t*)(baseA + ip*4)              = (uint32_t)h0a | ((uint32_t)h1a << 16);
                *(uint32_t*)(baseA + PLSTRIDE + ip*4)   = (uint32_t)m0a | ((uint32_t)m1a << 16);
                *(uint32_t*)(baseA + 2*PLSTRIDE + ip*4) = (uint32_t)l0a | ((uint32_t)l1a << 16);
            }
        }
        // B load: pre-split planes, 64B contiguous per thread per plane
        {
            size_t gb = (size_t)which*3*128*KLIN + (size_t)rowT*KLIN + kt + khT*32;
            char* baseB = dyn + B_OFF + rowT*144 + khT*64;
            #pragma unroll
            for (int pl = 0; pl < 3; pl++){
                const uint4* src = (const uint4*)(g_Wbf + gb + (size_t)pl*128*KLIN);
                uint4* dst = (uint4*)(baseB + pl*PLSTRIDE);
                dst[0]=src[0]; dst[1]=src[1]; dst[2]=src[2]; dst[3]=src[3];
            }
        }
        __syncthreads();
        // MMA: all fragments loaded, products interleaved across 16 accumulators
        #pragma unroll
        for (int s = 0; s < 4; s++){
            int kB = s*16;
            uint32_t aF[3][2][4];
            uint32_t aRow = (uint32_t)(mBase + (lane & 15));
            uint32_t aColB = (uint32_t)((kB + ((lane & 16) ? 8 : 0)) * 2);
            #pragma unroll
            for (int p = 0; p < 3; p++)
                #pragma unroll
                for (int mt = 0; mt < 2; mt++)
                    ldm4(aF[p][mt], sbase + A_OFF + p*PLSTRIDE + (aRow + mt*16)*144 + aColB);
            uint32_t bF[3][4][4];
            uint32_t nRow0 = (uint32_t)(nBase + (lane & 7) + ((lane & 16) ? 8 : 0));
            uint32_t bColB = (uint32_t)((kB + ((lane & 8) ? 8 : 0)) * 2);
            #pragma unroll
            for (int q = 0; q < 3; q++)
                #pragma unroll
                for (int np = 0; np < 4; np++)
                    ldm4(bF[q][np], sbase + B_OFF + q*PLSTRIDE + (nRow0 + np*16)*144 + bColB);
            const int PA[6] = {0,0,1,1,0,2};
            const int PB[6] = {0,1,0,1,2,0};
            #pragma unroll
            for (int pr = 0; pr < 6; pr++){
                const int pa = PA[pr], pb = PB[pr];
                #pragma unroll
                for (int np = 0; np < 4; np++){
                    #pragma unroll
                    for (int mt = 0; mt < 2; mt++){
                        mma16816(acc[mt][np*2],   aF[pa][mt], bF[pb][np][0], bF[pb][np][1]);
                        mma16816(acc[mt][np*2+1], aF[pa][mt], bF[pb][np][2], bF[pb][np][3]);
                    }
                }
            }
        }
        __syncthreads();
    }

    // epilogue: direct partial writes
    float* outp = g_partial + (size_t)kz*(BB*NJ);
    int gr = lane >> 2, gc = (lane & 3)*2;
    #pragma unroll
    for (int mt = 0; mt < 2; mt++){
        #pragma unroll
        for (int nt = 0; nt < 8; nt++){
            int row = m0 + mBase + mt*16 + gr;
            int col = nBase + nt*8 + gc;
            float* c = acc[mt][nt];
            *(float2*)&outp[(size_t)row*NJ + col]     = make_float2(c[0], c[1]);
            *(float2*)&outp[(size_t)(row+8)*NJ + col] = make_float2(c[2], c[3]);
        }
    }
}

__global__ void k_redsm(const float* __restrict__ bias){
    __shared__ float red[128];
    int b = blockIdx.x, t = threadIdx.x;
    float s = bias[t];
    #pragma unroll 8
    for (int kz=0; kz<SPLITK; kz++) s += g_partial[(size_t)(kz*BB + b)*NJ + t];
    float v = s;
    red[t] = v; __syncthreads();
    for (int st=64; st; st>>=1){ if (t < st) red[t] = fmaxf(red[t], red[t+st]); __syncthreads(); }
    float mx = red[0]; __syncthreads();
    float e = expf(v - mx);
    red[t] = e; __syncthreads();
    for (int st=64; st; st>>=1){ if (t < st) red[t] += red[t+st]; __syncthreads(); }
    g_vec[b*128 + t] = e / red[0];
}

__global__ void k_wsum(const float* __restrict__ mcw){
    int idx = blockIdx.x*256 + threadIdx.x;
    if (idx >= 3*64*128) return;
    int v = idx / 8192, rem = idx % 8192, base = rem*9 + 1;
    float w0 = mcw[base], w1 = mcw[base+3], w2 = mcw[base+6];
    g_Wsum[idx] = (v==0) ? (w1+w2) : (v==1) ? (w0+w1+w2) : (w0+w1);
}

__global__ void k_rgemm(const float* __restrict__ mcb){
    int idx = blockIdx.x*256 + threadIdx.x;
    if (idx >= 3*BB*64) return;
    int v = idx / (BB*64), rem = idx % (BB*64);
    int b = rem / 64, o = rem % 64;
    const float* eo = g_vec + b*128;
    const float* ws = g_Wsum + v*8192 + o*128;
    float s = mcb[o];
    for (int c=0;c<128;c++) s = fmaf(eo[c], ws[c], s);
    g_r[idx] = fmaxf(s, 0.f);
}

__global__ void k_lmid(const float* __restrict__ mlw){
    int idx = blockIdx.x*256 + threadIdx.x;
    if (idx >= 64*256) return;
    int o = idx >> 8, j = idx & 255;
    float s = 0.f;
    for (int h=1; h<127; h++) s += mlw[(size_t)(o*128 + h)*256 + j];
    g_Lmid[idx] = s;
}

__global__ void k_mtok(const float* __restrict__ mlw, const float* __restrict__ mlb){
    int idx = blockIdx.x*256 + threadIdx.x;
    if (idx >= BB*256) return;
    int b = idx >> 8, j = idx & 255;
    const float* r0   = g_r + 0*BB*64 + b*64;
    const float* ri   = g_r + 1*BB*64 + b*64;
    const float* r127 = g_r + 2*BB*64 + b*64;
    float s = mlb[j];
    for (int o=0; o<64; o++){
        s = fmaf(r0[o],   mlw[(size_t)o*32768 + j],          s);
        s = fmaf(ri[o],   g_Lmid[o*256 + j],                 s);
        s = fmaf(r127[o], mlw[(size_t)o*32768 + 32512 + j],  s);
    }
    int t = (int)floorf(fabsf(s) * 100.0f);
    g_tok[idx] = t % VV;
}

__global__ void k_redlin2(const float* __restrict__ bias, const float* __restrict__ w2,
                          const float* __restrict__ b2, float* __restrict__ out){
    __shared__ float f[128];
    int b = blockIdx.x, t = threadIdx.x;
    float s = bias[t];
    #pragma unroll 8
    for (int kz=0; kz<SPLITK; kz++) s += g_partial[(size_t)(kz*BB + b)*NJ + t];
    f[t] = s; __syncthreads();
    if (t < 32){
        float logit = -INFINITY;
        if (t < VV){
            logit = b2[t];
            for (int j=0; j<128; j++) logit = fmaf(f[j], w2[j*VV + t], logit);
        }
        float mx = logit;
        for (int off=16; off; off>>=1) mx = fmaxf(mx, __shfl_xor_sync(0xffffffffu, mx, off));
        float e = (t < VV) ? expf(logit - mx) : 0.f;
        float sm = e;
        for (int off=16; off; off>>=1) sm += __shfl_xor_sync(0xffffffffu, sm, off);
        if (t < VV) out[b*VV + t] = e / sm;
    }
}

extern "C" void kernel_launch(void* const* d_in, const int* in_sizes, int n_in,
                              void* d_out, int out_size){
    const int*   x    = (const int*)  d_in[0];
    const float* eemb = (const float*)d_in[1];
    const float* ecw  = (const float*)d_in[2];
    const float* ecb  = (const float*)d_in[3];
    const float* elw  = (const float*)d_in[4];
    const float* elb  = (const float*)d_in[5];
    const float* mcw  = (const float*)d_in[7];
    const float* mcb  = (const float*)d_in[8];
    const float* mlw  = (const float*)d_in[9];
    const float* mlb  = (const float*)d_in[10];
    const float* femb = (const float*)d_in[11];
    const float* fcw  = (const float*)d_in[12];
    const float* fcb  = (const float*)d_in[13];
    const float* flw1 = (const float*)d_in[14];
    const float* flb1 = (const float*)d_in[15];
    const float* flw2 = (const float*)d_in[16];
    const float* flb2 = (const float*)d_in[17];
    float* out = (float*)d_out;

    cudaFuncSetAttribute(k_gemmW, cudaFuncAttributeMaxDynamicSharedMemorySize, W_TOTAL);

    // LUT builds + W pre-split (both branches)
    k_poolT2<<<(2*EMBD*NPP)/256, 256>>>(eemb, femb);
    k_pbuild2<<<dim3(32,4,2), 512>>>(ecw, fcw);
    k_wsplit<<<dim3(1024,4,2), 256>>>(elw, flw1);
    k_pbreduce<<<(2*3*OC*NPP)/256, 256>>>();
    k_pairidx8<<<(HH*BB)/256, 256>>>(0, x);

    k_gemmW<<<dim3(2, SPLITK), 256, W_TOTAL>>>(0, ecb);
    k_redsm<<<BB, 128>>>(elb);

    k_wsum<<<(3*64*128)/256, 256>>>(mcw);
    k_rgemm<<<(3*BB*64)/256, 256>>>(mcb);
    k_lmid<<<(64*256)/256, 256>>>(mlw);
    k_mtok<<<(BB*256)/256, 256>>>(mlw, mlb);
    k_pairidx8<<<(HH*BB)/256, 256>>>(1, x);

    k_gemmW<<<dim3(2, SPLITK), 256, W_TOTAL>>>(1, fcb);
    k_redlin2<<<BB, 128>>>(flb1, flw2, flb2, out);
}

// round 12
// speedup vs baseline: 1.1250x; 1.1250x over previous
#include <cuda_runtime.h>
#include <math.h>

#define BB 256
#define LL 256
#define VV 14
#define EMBD 512
#define HH 128
#define OC 256
#define NP 196
#define NPP 256          // padded pair stride
#define KLIN 32768       // OC*HH
#define NJ 128
#define SPLITK 128
#define KC (KLIN/SPLITK) // 256 -> 2 output channels per split-K chunk

typedef unsigned long long ull;

// dynamic smem layout for k_gemmF
#define SM_AS    0                       // 2*16*128*4 = 16384
#define SM_BS    16384                   // 16384
#define SM_P2    32768                   // 6*256*4 = 6144
#define SM_SPI   38912                   // 128*132 = 16896
#define SM_BIAS  55808                   // 8
#define SM_TOTAL 55816

// ---------------- scratch ---------------------------------------------------
__device__ float g_poolT_e[EMBD*NPP];
__device__ float g_poolT_f[EMBD*NPP];
__device__ float g_pbpart[4*2*3*OC*NPP];   // [cs][br][kh][o][p]
__device__ float g_P2[2*3*OC*NPP];         // [br][kh][o][p]
__device__ unsigned char g_pi8T[2*HH*BB];  // [br][h][b] pair idx as uint8
__device__ float g_partial[SPLITK*BB*NJ];  // 16.8MB
__device__ float g_vec[BB*NJ];
__device__ float g_r[3*BB*64];
__device__ float g_Wsum[3*64*128];
__device__ float g_Lmid[64*256];
__device__ int   g_tok[BB*256];

// ---------------- f32x2 helpers --------------------------------------------
__device__ __forceinline__ ull pk2(float lo, float hi){
    ull r; asm("mov.b64 %0, {%1, %2};" : "=l"(r) : "f"(lo), "f"(hi)); return r;
}
__device__ __forceinline__ void upk2(ull v, float& lo, float& hi){
    asm("mov.b64 {%0, %1}, %2;" : "=f"(lo), "=f"(hi) : "l"(v));
}
__device__ __forceinline__ void ffma2(ull& c, ull a, ull b){
    asm("fma.rn.f32x2 %0, %1, %2, %0;" : "+l"(c) : "l"(a), "l"(b));
}

// ---------------- pooled-pair LUT, both branches ----------------------------
__global__ void k_poolT2(const float* __restrict__ eemb, const float* __restrict__ femb){
    int idx = blockIdx.x*256 + threadIdx.x;        // < 2*EMBD*NPP
    int br = idx / (EMBD*NPP);
    int r  = idx % (EMBD*NPP);
    int c = r >> 8, p = r & 255;
    const float* emb = br ? femb : eemb;
    float v = 0.f;
    if (p < NP){
        int t1 = p / VV, t2 = p % VV;
        v = fmaxf(emb[t1*EMBD + c], emb[t2*EMBD + c]);
    }
    (br ? g_poolT_f : g_poolT_e)[c*NPP + p] = v;
}

// ---------------- pbuild: P2 partials, c-split x4, both branches ------------
__global__ __launch_bounds__(512) void k_pbuild2(const float* __restrict__ ecw,
                                                 const float* __restrict__ fcw){
    int ot = blockIdx.x;          // 0..31 -> 8 o's
    int cs = blockIdx.y;          // 0..3  -> 128 c's
    int br = blockIdx.z;          // 0..1
    const float* cw    = br ? fcw : ecw;
    const float* poolT = br ? g_poolT_f : g_poolT_e;
    int o0 = ot*8, c0 = cs*128;
    __shared__ float ws[8*3*128];                 // [oi][kh][c]
    int tid = threadIdx.x;
    for (int e = tid; e < 3072; e += 512){
        int oi = e / 384, r = e % 384, kh = r >> 7, c = r & 127;
        ws[e] = cw[((size_t)(o0+oi)*EMBD + (c0+c))*9 + 1 + kh*3];
    }
    __syncthreads();
    int pg = tid & 63, oi = tid >> 6;
    int p0 = pg*4;
    ull a0=0,a1=0,a2=0,a3=0,a4=0,a5=0;   // [kh][pair]
    const float* pt  = poolT + (size_t)c0*NPP + p0;
    const float* wsp = ws + oi*384;
    #pragma unroll 4
    for (int c = 0; c < 128; c++){
        float4 pv = *(const float4*)(pt + (size_t)c*NPP);
        ull pa0 = pk2(pv.x, pv.y), pa1 = pk2(pv.z, pv.w);
        float w0 = wsp[c], w1 = wsp[128+c], w2 = wsp[256+c];
        ull b0 = pk2(w0,w0), b1 = pk2(w1,w1), b2 = pk2(w2,w2);
        ffma2(a0, pa0, b0); ffma2(a1, pa1, b0);
        ffma2(a2, pa0, b1); ffma2(a3, pa1, b1);
        ffma2(a4, pa0, b2); ffma2(a5, pa1, b2);
    }
    size_t base = (((size_t)(cs*2 + br)*3)*OC + (o0+oi))*NPP + p0;
    *(ulonglong2*)(g_pbpart + base)            = make_ulonglong2(a0, a1);
    *(ulonglong2*)(g_pbpart + base + OC*NPP)   = make_ulonglong2(a2, a3);
    *(ulonglong2*)(g_pbpart + base + 2*OC*NPP) = make_ulonglong2(a4, a5);
}

// ---------------- fused: P2 reduce + enemy pair indices ---------------------
// blocks [0,1536): pbreduce; blocks [1536,1664): pairidx8(which=0)
__global__ void k_pbredpair(const int* __restrict__ x){
    int blk = blockIdx.x;
    if (blk < 1536){
        int idx = blk*256 + threadIdx.x;           // < 2*3*OC*NPP
        int br = idx / (3*OC*NPP);
        int inner = idx % (3*OC*NPP);
        float s = g_pbpart[(0*2+br)*(3*OC*NPP) + inner]
                + g_pbpart[(1*2+br)*(3*OC*NPP) + inner]
                + g_pbpart[(2*2+br)*(3*OC*NPP) + inner]
                + g_pbpart[(3*2+br)*(3*OC*NPP) + inner];
        g_P2[idx] = s;
    } else {
        int idx = (blk - 1536)*256 + threadIdx.x;  // < HH*BB, idx = h*BB + b
        int b = idx & 255, h = idx >> 8;
        g_pi8T[idx] = (unsigned char)(x[b*LL + 2*h]*VV + x[b*LL + 2*h + 1]);
    }
}

// ---------------- friend pair indices ---------------------------------------
__global__ void k_pairidx8f(){
    int idx = blockIdx.x*256 + threadIdx.x;        // < HH*BB
    int b = idx & 255, h = idx >> 8;
    g_pi8T[HH*BB + idx] =
        (unsigned char)(g_tok[b*LL + 2*h]*VV + g_tok[b*LL + 2*h + 1]);
}

// ---------------- fused conv+GEMM, split-K, f32x2, double-buffered ----------
// grid (2, SPLITK), block 256. Tile 128(M) x 128(N), K-chunk KC=256 (2 o's).
__global__ __launch_bounds__(256) void k_gemmF(int which, const float* __restrict__ W,
                                               const float* __restrict__ bias){
    extern __shared__ char dyn[];
    float (*As)[16][128]      = (float(*)[16][128])(dyn + SM_AS);
    float (*Bs)[16][128]      = (float(*)[16][128])(dyn + SM_BS);
    float (*sP2)[256]         = (float(*)[256])(dyn + SM_P2);
    unsigned char (*spi)[132] = (unsigned char(*)[132])(dyn + SM_SPI);
    float* sbias              = (float*)(dyn + SM_BIAS);

    int tid = threadIdx.x;
    int m0 = blockIdx.x * 128;
    int k0 = blockIdx.y * KC;
    int o0 = k0 >> 7;
    int lk = tid & 15, lm = tid >> 4;
    int bj = tid & 127, bk = tid >> 7;
    int tx = tid & 15, ty = tid >> 4;

    const float* P2 = g_P2 + (size_t)which*(3*OC*NPP);
    for (int e = tid; e < 1536; e += 256){
        int kh = e / 512, r = e % 512, oi = r >> 8, p = r & 255;
        sP2[kh*2 + oi][p] = P2[(size_t)kh*OC*NPP + (o0+oi)*NPP + p];
    }
    const unsigned char* piT = g_pi8T + (size_t)which*(HH*BB);
    for (int e = tid; e < 4096; e += 256){
        int h = e >> 5, g = e & 31;
        *(uchar4*)&spi[h][g*4] = *(const uchar4*)(piT + h*BB + m0 + g*4);
    }
    if (tid < 2) sbias[tid] = bias[o0 + tid];
    __syncthreads();

    ull acc[4][8];
    #pragma unroll
    for (int i=0;i<4;i++)
        #pragma unroll
        for (int j=0;j<8;j++) acc[i][j] = 0ull;

    float ra[8], rb[8];
    auto computeA = [&](int t, float* r){
        int k = k0 + t + lk;
        int h = k & 127;
        int oi = (k >> 7) - o0;
        const float* p2a = sP2[0 + oi];
        const float* p2b = sP2[2 + oi];
        const float* p2c = sP2[4 + oi];
        float vb = sbias[oi];
        bool hasA = (h > 0), hasC = (h < 127);
        #pragma unroll
        for (int i=0;i<8;i++){
            int m = lm + i*16;
            float v = vb;
            if (hasA) v += p2a[spi[h-1][m]];
            v += p2b[spi[h][m]];
            if (hasC) v += p2c[spi[h+1][m]];
            r[i] = v;
        }
    };

    computeA(0, ra);
    #pragma unroll
    for (int i=0;i<8;i++) rb[i] = W[(size_t)(k0 + bk + i*2)*NJ + bj];
    #pragma unroll
    for (int i=0;i<8;i++) As[0][lk][lm + i*16] = ra[i];
    #pragma unroll
    for (int i=0;i<8;i++) Bs[0][bk + i*2][bj] = rb[i];
    __syncthreads();

    int buf = 0;
    for (int t = 16; t < KC; t += 16){
        computeA(t, ra);
        #pragma unroll
        for (int i=0;i<8;i++) rb[i] = W[(size_t)(k0 + t + bk + i*2)*NJ + bj];
        #pragma unroll
        for (int kk=0; kk<16; kk++){
            float4 a0 = *(const float4*)&As[buf][kk][ty*8];
            float4 a1 = *(const float4*)&As[buf][kk][ty*8 + 4];
            float4 b0 = *(const float4*)&Bs[buf][kk][tx*4];
            float4 b1 = *(const float4*)&Bs[buf][kk][64 + tx*4];
            ull ap[4] = { pk2(a0.x,a0.y), pk2(a0.z,a0.w),
                          pk2(a1.x,a1.y), pk2(a1.z,a1.w) };
            ull bd[8] = { pk2(b0.x,b0.x), pk2(b0.y,b0.y),
                          pk2(b0.z,b0.z), pk2(b0.w,b0.w),
                          pk2(b1.x,b1.x), pk2(b1.y,b1.y),
                          pk2(b1.z,b1.z), pk2(b1.w,b1.w) };
            #pragma unroll
            for (int i=0;i<4;i++)
                #pragma unroll
                for (int j=0;j<8;j++)
                    ffma2(acc[i][j], ap[i], bd[j]);
        }
        #pragma unroll
        for (int i=0;i<8;i++) As[buf^1][lk][lm + i*16] = ra[i];
        #pragma unroll
        for (int i=0;i<8;i++) Bs[buf^1][bk + i*2][bj] = rb[i];
        __syncthreads();
        buf ^= 1;
    }
    #pragma unroll
    for (int kk=0; kk<16; kk++){
        float4 a0 = *(const float4*)&As[buf][kk][ty*8];
        float4 a1 = *(const float4*)&As[buf][kk][ty*8 + 4];
        float4 b0 = *(const float4*)&Bs[buf][kk][tx*4];
        float4 b1 = *(const float4*)&Bs[buf][kk][64 + tx*4];
        ull ap[4] = { pk2(a0.x,a0.y), pk2(a0.z,a0.w),
                      pk2(a1.x,a1.y), pk2(a1.z,a1.w) };
        ull bd[8] = { pk2(b0.x,b0.x), pk2(b0.y,b0.y),
                      pk2(b0.z,b0.z), pk2(b0.w,b0.w),
                      pk2(b1.x,b1.x), pk2(b1.y,b1.y),
                      pk2(b1.z,b1.z), pk2(b1.w,b1.w) };
        #pragma unroll
        for (int i=0;i<4;i++)
            #pragma unroll
            for (int j=0;j<8;j++)
                ffma2(acc[i][j], ap[i], bd[j]);
    }

    float* outp = g_partial + (size_t)blockIdx.y * (BB*NJ);
    #pragma unroll
    for (int i=0;i<4;i++){
        int mlo = m0 + ty*8 + 2*i;
        float rlo[8], rhi[8];
        #pragma unroll
        for (int j=0;j<8;j++) upk2(acc[i][j], rlo[j], rhi[j]);
        *(float4*)&outp[(size_t)mlo*NJ + tx*4]          = make_float4(rlo[0],rlo[1],rlo[2],rlo[3]);
        *(float4*)&outp[(size_t)mlo*NJ + 64 + tx*4]     = make_float4(rlo[4],rlo[5],rlo[6],rlo[7]);
        *(float4*)&outp[(size_t)(mlo+1)*NJ + tx*4]      = make_float4(rhi[0],rhi[1],rhi[2],rhi[3]);
        *(float4*)&outp[(size_t)(mlo+1)*NJ + 64 + tx*4] = make_float4(rhi[4],rhi[5],rhi[6],rhi[7]);
    }
}

// ---------------- split-K reduce + softmax (enemy) --------------------------
__global__ void k_redsm(const float* __restrict__ bias){
    __shared__ float red[128];
    int b = blockIdx.x, t = threadIdx.x;
    float s = bias[t];
    #pragma unroll 8
    for (int kz=0; kz<SPLITK; kz++) s += g_partial[(size_t)(kz*BB + b)*NJ + t];
    float v = s;
    red[t] = v; __syncthreads();
    for (int st=64; st; st>>=1){ if (t < st) red[t] = fmaxf(red[t], red[t+st]); __syncthreads(); }
    float mx = red[0]; __syncthreads();
    float e = expf(v - mx);
    red[t] = e; __syncthreads();
    for (int st=64; st; st>>=1){ if (t < st) red[t] += red[t+st]; __syncthreads(); }
    g_vec[b*128 + t] = e / red[0];
}

// ---------------- fused: manipulator weight-sum + lin row-sum ---------------
// blocks [0,96): wsum; blocks [96,160): lmid
__global__ void k_wsumlmid(const float* __restrict__ mcw, const float* __restrict__ mlw){
    int blk = blockIdx.x;
    if (blk < 96){
        int idx = blk*256 + threadIdx.x;     // < 3*64*128
        int v = idx / 8192;
        int rem = idx % 8192;
        int base = rem*9 + 1;
        float w0 = mcw[base], w1 = mcw[base+3], w2 = mcw[base+6];
        g_Wsum[idx] = (v==0) ? (w1+w2) : (v==1) ? (w0+w1+w2) : (w0+w1);
    } else {
        int idx = (blk-96)*256 + threadIdx.x; // < 64*256
        int o = idx >> 8, j = idx & 255;
        float s = 0.f;
        for (int h=1; h<127; h++) s += mlw[(size_t)(o*128 + h)*256 + j];
        g_Lmid[idx] = s;
    }
}

__global__ void k_rgemm(const float* __restrict__ mcb){
    int idx = blockIdx.x*256 + threadIdx.x;     // < 3*BB*64
    if (idx >= 3*BB*64) return;
    int v = idx / (BB*64);
    int rem = idx % (BB*64);
    int b = rem / 64, o = rem % 64;
    const float* eo = g_vec + b*128;
    const float* ws = g_Wsum + v*8192 + o*128;
    float s = mcb[o];
    for (int c=0;c<128;c++) s = fmaf(eo[c], ws[c], s);
    g_r[idx] = fmaxf(s, 0.f);
}

__global__ void k_mtok(const float* __restrict__ mlw, const float* __restrict__ mlb){
    int idx = blockIdx.x*256 + threadIdx.x;     // < BB*256
    if (idx >= BB*256) return;
    int b = idx >> 8, j = idx & 255;
    const float* r0   = g_r + 0*BB*64 + b*64;
    const float* ri   = g_r + 1*BB*64 + b*64;
    const float* r127 = g_r + 2*BB*64 + b*64;
    float s = mlb[j];
    for (int o=0; o<64; o++){
        s = fmaf(r0[o],   mlw[(size_t)o*32768 + j],          s);
        s = fmaf(ri[o],   g_Lmid[o*256 + j],                 s);
        s = fmaf(r127[o], mlw[(size_t)o*32768 + 32512 + j],  s);
    }
    int t = (int)floorf(fabsf(s) * 100.0f);
    g_tok[idx] = t % VV;
}

// ---------------- friend: reduce + final linear + softmax -------------------
__global__ void k_redlin2(const float* __restrict__ bias, const float* __restrict__ w2,
                          const float* __restrict__ b2, float* __restrict__ out){
    __shared__ float f[128];
    int b = blockIdx.x, t = threadIdx.x;
    float s = bias[t];
    #pragma unroll 8
    for (int kz=0; kz<SPLITK; kz++) s += g_partial[(size_t)(kz*BB + b)*NJ + t];
    f[t] = s; __syncthreads();
    if (t < 32){
        float logit = -INFINITY;
        if (t < VV){
            logit = b2[t];
            for (int j=0; j<128; j++) logit = fmaf(f[j], w2[j*VV + t], logit);
        }
        float mx = logit;
        for (int off=16; off; off>>=1) mx = fmaxf(mx, __shfl_xor_sync(0xffffffffu, mx, off));
        float e = (t < VV) ? expf(logit - mx) : 0.f;
        float sm = e;
        for (int off=16; off; off>>=1) sm += __shfl_xor_sync(0xffffffffu, sm, off);
        if (t < VV) out[b*VV + t] = e / sm;
    }
}

// ---------------- launch ----------------------------------------------------
extern "C" void kernel_launch(void* const* d_in, const int* in_sizes, int n_in,
                              void* d_out, int out_size){
    const int*   x    = (const int*)  d_in[0];
    const float* eemb = (const float*)d_in[1];
    const float* ecw  = (const float*)d_in[2];
    const float* ecb  = (const float*)d_in[3];
    const float* elw  = (const float*)d_in[4];
    const float* elb  = (const float*)d_in[5];
    // d_in[6] rand_proj: dead (fog_of_war == identity permutation)
    const float* mcw  = (const float*)d_in[7];
    const float* mcb  = (const float*)d_in[8];
    const float* mlw  = (const float*)d_in[9];
    const float* mlb  = (const float*)d_in[10];
    const float* femb = (const float*)d_in[11];
    const float* fcw  = (const float*)d_in[12];
    const float* fcb  = (const float*)d_in[13];
    const float* flw1 = (const float*)d_in[14];
    const float* flb1 = (const float*)d_in[15];
    const float* flw2 = (const float*)d_in[16];
    const float* flb2 = (const float*)d_in[17];
    float* out = (float*)d_out;

    cudaFuncSetAttribute(k_gemmF, cudaFuncAttributeMaxDynamicSharedMemorySize, SM_TOTAL);

    // LUT builds; gemmF is the 4th launch (ncu profiles launch #4)
    k_poolT2<<<(2*EMBD*NPP)/256, 256>>>(eemb, femb);           // 1
    k_pbuild2<<<dim3(32,4,2), 512>>>(ecw, fcw);                // 2
    k_pbredpair<<<1664, 256>>>(x);                             // 3 (P2 reduce + enemy pairidx)

    // enemy branch (conv fused into GEMM)
    k_gemmF<<<dim3(2, SPLITK), 256, SM_TOTAL>>>(0, elw, ecb);  // 4 <- profiled
    k_redsm<<<BB, 128>>>(elb);                                 // 5

    // manipulator -> tokens
    k_wsumlmid<<<160, 256>>>(mcw, mlw);                        // 6
    k_rgemm<<<(3*BB*64)/256, 256>>>(mcb);                      // 7
    k_mtok<<<(BB*256)/256, 256>>>(mlw, mlb);                   // 8
    k_pairidx8f<<<(HH*BB)/256, 256>>>();                       // 9

    // friend branch (conv fused into GEMM)
    k_gemmF<<<dim3(2, SPLITK), 256, SM_TOTAL>>>(1, flw1, fcb); // 10
    k_redlin2<<<BB, 128>>>(flb1, flw2, flb2, out);             // 11
}

// round 13
// speedup vs baseline: 1.1944x; 1.0617x over previous
#include <cuda_runtime.h>
#include <math.h>

#define BB 256
#define LL 256
#define VV 14
#define EMBD 512
#define HH 128
#define OC 256
#define NP 196
#define NPP 256          // padded pair stride
#define KLIN 32768       // OC*HH
#define NJ 128
#define SPLITK 128
#define KC (KLIN/SPLITK) // 256 -> 2 output channels per split-K chunk

typedef unsigned long long ull;

// dynamic smem layout for k_gemmF
#define SM_AS    0                       // 2*16*128*4 = 16384
#define SM_BS    16384                   // 16384
#define SM_P2    32768                   // 6*256*4 = 6144
#define SM_SPI   38912                   // 128*132 = 16896
#define SM_BIAS  55808                   // 8
#define SM_TOTAL 55816

// ---------------- scratch ---------------------------------------------------
__device__ float g_poolT_e[EMBD*NPP];
__device__ float g_poolT_f[EMBD*NPP];
__device__ float g_pbpart[4*2*3*OC*NPP];   // [cs][br][kh][o][p]
__device__ float g_P2[2*3*OC*NPP];         // [br][kh][o][p]
__device__ unsigned char g_pi8T[2*HH*BB];  // [br][h][b] pair idx as uint8
__device__ float g_partial[SPLITK*BB*NJ];  // 16.8MB
__device__ float g_r[3*BB*64];
__device__ float g_Wsum[3*64*128];
__device__ float g_Lmid[64*256];

// ---------------- f32x2 helpers --------------------------------------------
__device__ __forceinline__ ull pk2(float lo, float hi){
    ull r; asm("mov.b64 %0, {%1, %2};" : "=l"(r) : "f"(lo), "f"(hi)); return r;
}
__device__ __forceinline__ void upk2(ull v, float& lo, float& hi){
    asm("mov.b64 {%0, %1}, %2;" : "=f"(lo), "=f"(hi) : "l"(v));
}
__device__ __forceinline__ void ffma2(ull& c, ull a, ull b){
    asm("fma.rn.f32x2 %0, %1, %2, %0;" : "+l"(c) : "l"(a), "l"(b));
}

// ---------------- pooled-pair LUT, both branches ----------------------------
__global__ void k_poolT2(const float* __restrict__ eemb, const float* __restrict__ femb){
    int idx = blockIdx.x*256 + threadIdx.x;        // < 2*EMBD*NPP
    int br = idx / (EMBD*NPP);
    int r  = idx % (EMBD*NPP);
    int c = r >> 8, p = r & 255;
    const float* emb = br ? femb : eemb;
    float v = 0.f;
    if (p < NP){
        int t1 = p / VV, t2 = p % VV;
        v = fmaxf(emb[t1*EMBD + c], emb[t2*EMBD + c]);
    }
    (br ? g_poolT_f : g_poolT_e)[c*NPP + p] = v;
}

// ---------------- pbuild: P2 partials, c-split x4, both branches ------------
__global__ __launch_bounds__(512) void k_pbuild2(const float* __restrict__ ecw,
                                                 const float* __restrict__ fcw){
    int ot = blockIdx.x;          // 0..31 -> 8 o's
    int cs = blockIdx.y;          // 0..3  -> 128 c's
    int br = blockIdx.z;          // 0..1
    const float* cw    = br ? fcw : ecw;
    const float* poolT = br ? g_poolT_f : g_poolT_e;
    int o0 = ot*8, c0 = cs*128;
    __shared__ float ws[8*3*128];                 // [oi][kh][c]
    int tid = threadIdx.x;
    for (int e = tid; e < 3072; e += 512){
        int oi = e / 384, r = e % 384, kh = r >> 7, c = r & 127;
        ws[e] = cw[((size_t)(o0+oi)*EMBD + (c0+c))*9 + 1 + kh*3];
    }
    __syncthreads();
    int pg = tid & 63, oi = tid >> 6;
    int p0 = pg*4;
    ull a0=0,a1=0,a2=0,a3=0,a4=0,a5=0;   // [kh][pair]
    const float* pt  = poolT + (size_t)c0*NPP + p0;
    const float* wsp = ws + oi*384;
    #pragma unroll 4
    for (int c = 0; c < 128; c++){
        float4 pv = *(const float4*)(pt + (size_t)c*NPP);
        ull pa0 = pk2(pv.x, pv.y), pa1 = pk2(pv.z, pv.w);
        float w0 = wsp[c], w1 = wsp[128+c], w2 = wsp[256+c];
        ull b0 = pk2(w0,w0), b1 = pk2(w1,w1), b2 = pk2(w2,w2);
        ffma2(a0, pa0, b0); ffma2(a1, pa1, b0);
        ffma2(a2, pa0, b1); ffma2(a3, pa1, b1);
        ffma2(a4, pa0, b2); ffma2(a5, pa1, b2);
    }
    size_t base = (((size_t)(cs*2 + br)*3)*OC + (o0+oi))*NPP + p0;
    *(ulonglong2*)(g_pbpart + base)            = make_ulonglong2(a0, a1);
    *(ulonglong2*)(g_pbpart + base + OC*NPP)   = make_ulonglong2(a2, a3);
    *(ulonglong2*)(g_pbpart + base + 2*OC*NPP) = make_ulonglong2(a4, a5);
}

// ---------------- prep: P2 reduce + enemy pairidx + wsum + lmid -------------
// blocks [0,1536): pbreduce; [1536,1664): enemy pairidx;
// [1664,1760): manip wsum; [1760,1824): manip lin row-sum
__global__ void k_prep(const int* __restrict__ x, const float* __restrict__ mcw,
                       const float* __restrict__ mlw){
    int blk = blockIdx.x;
    if (blk < 1536){
        int idx = blk*256 + threadIdx.x;           // < 2*3*OC*NPP
        int br = idx / (3*OC*NPP);
        int inner = idx % (3*OC*NPP);
        float s = g_pbpart[(0*2+br)*(3*OC*NPP) + inner]
                + g_pbpart[(1*2+br)*(3*OC*NPP) + inner]
                + g_pbpart[(2*2+br)*(3*OC*NPP) + inner]
                + g_pbpart[(3*2+br)*(3*OC*NPP) + inner];
        g_P2[idx] = s;
    } else if (blk < 1664){
        int idx = (blk - 1536)*256 + threadIdx.x;  // < HH*BB, idx = h*BB + b
        int b = idx & 255, h = idx >> 8;
        g_pi8T[idx] = (unsigned char)(x[b*LL + 2*h]*VV + x[b*LL + 2*h + 1]);
    } else if (blk < 1760){
        int idx = (blk - 1664)*256 + threadIdx.x;  // < 3*64*128
        int v = idx / 8192;
        int rem = idx % 8192;
        int base = rem*9 + 1;
        float w0 = mcw[base], w1 = mcw[base+3], w2 = mcw[base+6];
        g_Wsum[idx] = (v==0) ? (w1+w2) : (v==1) ? (w0+w1+w2) : (w0+w1);
    } else {
        int idx = (blk - 1760)*256 + threadIdx.x;  // < 64*256
        int o = idx >> 8, j = idx & 255;
        float s = 0.f;
        for (int h=1; h<127; h++) s += mlw[(size_t)(o*128 + h)*256 + j];
        g_Lmid[idx] = s;
    }
}

// ---------------- fused conv+GEMM, split-K, f32x2, double-buffered ----------
__global__ __launch_bounds__(256) void k_gemmF(int which, const float* __restrict__ W,
                                               const float* __restrict__ bias){
    extern __shared__ char dyn[];
    float (*As)[16][128]      = (float(*)[16][128])(dyn + SM_AS);
    float (*Bs)[16][128]      = (float(*)[16][128])(dyn + SM_BS);
    float (*sP2)[256]         = (float(*)[256])(dyn + SM_P2);
    unsigned char (*spi)[132] = (unsigned char(*)[132])(dyn + SM_SPI);
    float* sbias              = (float*)(dyn + SM_BIAS);

    int tid = threadIdx.x;
    int m0 = blockIdx.x * 128;
    int k0 = blockIdx.y * KC;
    int o0 = k0 >> 7;
    int lk = tid & 15, lm = tid >> 4;
    int bj = tid & 127, bk = tid >> 7;
    int tx = tid & 15, ty = tid >> 4;

    const float* P2 = g_P2 + (size_t)which*(3*OC*NPP);
    for (int e = tid; e < 1536; e += 256){
        int kh = e / 512, r = e % 512, oi = r >> 8, p = r & 255;
        sP2[kh*2 + oi][p] = P2[(size_t)kh*OC*NPP + (o0+oi)*NPP + p];
    }
    const unsigned char* piT = g_pi8T + (size_t)which*(HH*BB);
    for (int e = tid; e < 4096; e += 256){
        int h = e >> 5, g = e & 31;
        *(uchar4*)&spi[h][g*4] = *(const uchar4*)(piT + h*BB + m0 + g*4);
    }
    if (tid < 2) sbias[tid] = bias[o0 + tid];
    __syncthreads();

    ull acc[4][8];
    #pragma unroll
    for (int i=0;i<4;i++)
        #pragma unroll
        for (int j=0;j<8;j++) acc[i][j] = 0ull;

    float ra[8], rb[8];
    auto computeA = [&](int t, float* r){
        int k = k0 + t + lk;
        int h = k & 127;
        int oi = (k >> 7) - o0;
        const float* p2a = sP2[0 + oi];
        const float* p2b = sP2[2 + oi];
        const float* p2c = sP2[4 + oi];
        float vb = sbias[oi];
        bool hasA = (h > 0), hasC = (h < 127);
        #pragma unroll
        for (int i=0;i<8;i++){
            int m = lm + i*16;
            float v = vb;
            if (hasA) v += p2a[spi[h-1][m]];
            v += p2b[spi[h][m]];
            if (hasC) v += p2c[spi[h+1][m]];
            r[i] = v;
        }
    };

    computeA(0, ra);
    #pragma unroll
    for (int i=0;i<8;i++) rb[i] = W[(size_t)(k0 + bk + i*2)*NJ + bj];
    #pragma unroll
    for (int i=0;i<8;i++) As[0][lk][lm + i*16] = ra[i];
    #pragma unroll
    for (int i=0;i<8;i++) Bs[0][bk + i*2][bj] = rb[i];
    __syncthreads();

    int buf = 0;
    for (int t = 16; t < KC; t += 16){
        computeA(t, ra);
        #pragma unroll
        for (int i=0;i<8;i++) rb[i] = W[(size_t)(k0 + t + bk + i*2)*NJ + bj];
        #pragma unroll
        for (int kk=0; kk<16; kk++){
            ulonglong2 a01 = *(const ulonglong2*)&As[buf][kk][ty*8];
            ulonglong2 a23 = *(const ulonglong2*)&As[buf][kk][ty*8 + 4];
            float4 b0 = *(const float4*)&Bs[buf][kk][tx*4];
            float4 b1 = *(const float4*)&Bs[buf][kk][64 + tx*4];
            ull ap[4] = { a01.x, a01.y, a23.x, a23.y };
            ull bd[8] = { pk2(b0.x,b0.x), pk2(b0.y,b0.y),
                          pk2(b0.z,b0.z), pk2(b0.w,b0.w),
                          pk2(b1.x,b1.x), pk2(b1.y,b1.y),
                          pk2(b1.z,b1.z), pk2(b1.w,b1.w) };
            #pragma unroll
            for (int i=0;i<4;i++)
                #pragma unroll
                for (int j=0;j<8;j++)
                    ffma2(acc[i][j], ap[i], bd[j]);
        }
        #pragma unroll
        for (int i=0;i<8;i++) As[buf^1][lk][lm + i*16] = ra[i];
        #pragma unroll
        for (int i=0;i<8;i++) Bs[buf^1][bk + i*2][bj] = rb[i];
        __syncthreads();
        buf ^= 1;
    }
    #pragma unroll
    for (int kk=0; kk<16; kk++){
        ulonglong2 a01 = *(const ulonglong2*)&As[buf][kk][ty*8];
        ulonglong2 a23 = *(const ulonglong2*)&As[buf][kk][ty*8 + 4];
        float4 b0 = *(const float4*)&Bs[buf][kk][tx*4];
        float4 b1 = *(const float4*)&Bs[buf][kk][64 + tx*4];
        ull ap[4] = { a01.x, a01.y, a23.x, a23.y };
        ull bd[8] = { pk2(b0.x,b0.x), pk2(b0.y,b0.y),
                      pk2(b0.z,b0.z), pk2(b0.w,b0.w),
                      pk2(b1.x,b1.x), pk2(b1.y,b1.y),
                      pk2(b1.z,b1.z), pk2(b1.w,b1.w) };
        #pragma unroll
        for (int i=0;i<4;i++)
            #pragma unroll
            for (int j=0;j<8;j++)
                ffma2(acc[i][j], ap[i], bd[j]);
    }

    float* outp = g_partial + (size_t)blockIdx.y * (BB*NJ);
    #pragma unroll
    for (int i=0;i<4;i++){
        int mlo = m0 + ty*8 + 2*i;
        float rlo[8], rhi[8];
        #pragma unroll
        for (int j=0;j<8;j++) upk2(acc[i][j], rlo[j], rhi[j]);
        *(float4*)&outp[(size_t)mlo*NJ + tx*4]          = make_float4(rlo[0],rlo[1],rlo[2],rlo[3]);
        *(float4*)&outp[(size_t)mlo*NJ + 64 + tx*4]     = make_float4(rlo[4],rlo[5],rlo[6],rlo[7]);
        *(float4*)&outp[(size_t)(mlo+1)*NJ + tx*4]      = make_float4(rhi[0],rhi[1],rhi[2],rhi[3]);
        *(float4*)&outp[(size_t)(mlo+1)*NJ + 64 + tx*4] = make_float4(rhi[4],rhi[5],rhi[6],rhi[7]);
    }
}

// ---------------- enemy: split-K reduce + softmax + manip conv GEMM ---------
__global__ void k_redsmrg(const float* __restrict__ bias, const float* __restrict__ mcb){
    __shared__ float red[128];
    __shared__ float eo[128];
    int b = blockIdx.x, t = threadIdx.x;
    float s = bias[t];
    #pragma unroll 8
    for (int kz=0; kz<SPLITK; kz++) s += g_partial[(size_t)(kz*BB + b)*NJ + t];
    float v = s;
    red[t] = v; __syncthreads();
    for (int st=64; st; st>>=1){ if (t < st) red[t] = fmaxf(red[t], red[t+st]); __syncthreads(); }
    float mx = red[0]; __syncthreads();
    float e = expf(v - mx);
    red[t] = e; __syncthreads();
    for (int st=64; st; st>>=1){ if (t < st) red[t] += red[t+st]; __syncthreads(); }
    eo[t] = e / red[0];
    __syncthreads();
    // manipulator conv (collapsed): r[v][b][o], 192 outputs per block
    for (int e2 = t; e2 < 192; e2 += 128){
        int vv = e2 >> 6, o = e2 & 63;
        const float* ws = g_Wsum + vv*8192 + o*128;
        float acc = mcb[o];
        for (int c=0;c<128;c++) acc = fmaf(eo[c], ws[c], acc);
        g_r[vv*BB*64 + b*64 + o] = fmaxf(acc, 0.f);
    }
}

// ---------------- manip linear -> tokens -> friend pair indices -------------
__global__ void k_mtokpair(const float* __restrict__ mlw, const float* __restrict__ mlb){
    __shared__ unsigned char stok[256];
    int b = blockIdx.x, j = threadIdx.x;    // 256 threads
    const float* r0   = g_r + 0*BB*64 + b*64;
    const float* ri   = g_r + 1*BB*64 + b*64;
    const float* r127 = g_r + 2*BB*64 + b*64;
    float s = mlb[j];
    for (int o=0; o<64; o++){
        s = fmaf(r0[o],   mlw[(size_t)o*32768 + j],          s);
        s = fmaf(ri[o],   g_Lmid[o*256 + j],                 s);
        s = fmaf(r127[o], mlw[(size_t)o*32768 + 32512 + j],  s);
    }
    int tk = (int)floorf(fabsf(s) * 100.0f);
    stok[j] = (unsigned char)(tk % VV);
    __syncthreads();
    if (j < 128)
        g_pi8T[HH*BB + j*BB + b] = (unsigned char)(stok[2*j]*VV + stok[2*j+1]);
}

// ---------------- friend: reduce + final linear + softmax -------------------
__global__ void k_redlin2(const float* __restrict__ bias, const float* __restrict__ w2,
                          const float* __restrict__ b2, float* __restrict__ out){
    __shared__ float f[128];
    int b = blockIdx.x, t = threadIdx.x;
    float s = bias[t];
    #pragma unroll 8
    for (int kz=0; kz<SPLITK; kz++) s += g_partial[(size_t)(kz*BB + b)*NJ + t];
    f[t] = s; __syncthreads();
    if (t < 32){
        float logit = -INFINITY;
        if (t < VV){
            logit = b2[t];
            for (int j=0; j<128; j++) logit = fmaf(f[j], w2[j*VV + t], logit);
        }
        float mx = logit;
        for (int off=16; off; off>>=1) mx = fmaxf(mx, __shfl_xor_sync(0xffffffffu, mx, off));
        float e = (t < VV) ? expf(logit - mx) : 0.f;
        float sm = e;
        for (int off=16; off; off>>=1) sm += __shfl_xor_sync(0xffffffffu, sm, off);
        if (t < VV) out[b*VV + t] = e / sm;
    }
}

// ---------------- launch ----------------------------------------------------
extern "C" void kernel_launch(void* const* d_in, const int* in_sizes, int n_in,
                              void* d_out, int out_size){
    const int*   x    = (const int*)  d_in[0];
    const float* eemb = (const float*)d_in[1];
    const float* ecw  = (const float*)d_in[2];
    const float* ecb  = (const float*)d_in[3];
    const float* elw  = (const float*)d_in[4];
    const float* elb  = (const float*)d_in[5];
    // d_in[6] rand_proj: dead (fog_of_war == identity permutation)
    const float* mcw  = (const float*)d_in[7];
    const float* mcb  = (const float*)d_in[8];
    const float* mlw  = (const float*)d_in[9];
    const float* mlb  = (const float*)d_in[10];
    const float* femb = (const float*)d_in[11];
    const float* fcw  = (const float*)d_in[12];
    const float* fcb  = (const float*)d_in[13];
    const float* flw1 = (const float*)d_in[14];
    const float* flb1 = (const float*)d_in[15];
    const float* flw2 = (const float*)d_in[16];
    const float* flb2 = (const float*)d_in[17];
    float* out = (float*)d_out;

    cudaFuncSetAttribute(k_gemmF, cudaFuncAttributeMaxDynamicSharedMemorySize, SM_TOTAL);

    k_poolT2<<<(2*EMBD*NPP)/256, 256>>>(eemb, femb);           // 1
    k_pbuild2<<<dim3(32,4,2), 512>>>(ecw, fcw);                // 2
    k_prep<<<1824, 256>>>(x, mcw, mlw);                        // 3

    k_gemmF<<<dim3(2, SPLITK), 256, SM_TOTAL>>>(0, elw, ecb);  // 4 <- profiled
    k_redsmrg<<<BB, 128>>>(elb, mcb);                          // 5
    k_mtokpair<<<BB, 256>>>(mlw, mlb);                         // 6

    k_gemmF<<<dim3(2, SPLITK), 256, SM_TOTAL>>>(1, flw1, fcb); // 7
    k_redlin2<<<BB, 128>>>(flb1, flw2, flb2, out);             // 8
}

// round 14
// speedup vs baseline: 1.3634x; 1.1415x over previous
#include <cuda_runtime.h>
#include <math.h>

#define BB 256
#define LL 256
#define VV 14
#define EMBD 512
#define HH 128
#define OC 256
#define NP 196
#define NPP 256          // padded pair stride
#define KLIN 32768       // OC*HH
#define NJ 128
#define SPLITK 128
#define KC (KLIN/SPLITK) // 256 -> 2 output channels per split-K chunk

typedef unsigned long long ull;

// dynamic smem layout for k_gemmF (As rows padded to 132 floats: kills the
// 16-way bank conflict on A-staging stores; 528B rows stay 16B-aligned)
#define SM_AS    0                       // 2*16*132*4 = 16896
#define SM_BS    16896                   // 2*16*128*4 = 16384
#define SM_P2    33280                   // 6*256*4 = 6144
#define SM_SPI   39424                   // 128*132 = 16896
#define SM_BIAS  56320                   // 8
#define SM_TOTAL 56328

// ---------------- scratch ---------------------------------------------------
__device__ float g_poolT_e[EMBD*NPP];
__device__ float g_poolT_f[EMBD*NPP];
__device__ float g_pbpart[4*2*3*OC*NPP];   // [cs][br][kh][o][p]
__device__ float g_P2[2*3*OC*NPP];         // [br][kh][o][p]
__device__ unsigned char g_pi8T[2*HH*BB];  // [br][h][b] pair idx as uint8
__device__ float g_partial[SPLITK*BB*NJ];  // 16.8MB
__device__ float g_Wsum[3*64*128];
__device__ float g_Lmid[64*256];

// ---------------- f32x2 helpers --------------------------------------------
__device__ __forceinline__ ull pk2(float lo, float hi){
    ull r; asm("mov.b64 %0, {%1, %2};" : "=l"(r) : "f"(lo), "f"(hi)); return r;
}
__device__ __forceinline__ void upk2(ull v, float& lo, float& hi){
    asm("mov.b64 {%0, %1}, %2;" : "=f"(lo), "=f"(hi) : "l"(v));
}
__device__ __forceinline__ void ffma2(ull& c, ull a, ull b){
    asm("fma.rn.f32x2 %0, %1, %2, %0;" : "+l"(c) : "l"(a), "l"(b));
}

// ---------------- pooled-pair LUT, both branches ----------------------------
__global__ void k_poolT2(const float* __restrict__ eemb, const float* __restrict__ femb){
    int idx = blockIdx.x*256 + threadIdx.x;        // < 2*EMBD*NPP
    int br = idx / (EMBD*NPP);
    int r  = idx % (EMBD*NPP);
    int c = r >> 8, p = r & 255;
    const float* emb = br ? femb : eemb;
    float v = 0.f;
    if (p < NP){
        int t1 = p / VV, t2 = p % VV;
        v = fmaxf(emb[t1*EMBD + c], emb[t2*EMBD + c]);
    }
    (br ? g_poolT_f : g_poolT_e)[c*NPP + p] = v;
}

// ---------------- pbuild: P2 partials, c-split x4, both branches ------------
__global__ __launch_bounds__(512) void k_pbuild2(const float* __restrict__ ecw,
                                                 const float* __restrict__ fcw){
    int ot = blockIdx.x;          // 0..31 -> 8 o's
    int cs = blockIdx.y;          // 0..3  -> 128 c's
    int br = blockIdx.z;          // 0..1
    const float* cw    = br ? fcw : ecw;
    const float* poolT = br ? g_poolT_f : g_poolT_e;
    int o0 = ot*8, c0 = cs*128;
    __shared__ float ws[8*3*128];                 // [oi][kh][c]
    int tid = threadIdx.x;
    for (int e = tid; e < 3072; e += 512){
        int oi = e / 384, r = e % 384, kh = r >> 7, c = r & 127;
        ws[e] = cw[((size_t)(o0+oi)*EMBD + (c0+c))*9 + 1 + kh*3];
    }
    __syncthreads();
    int pg = tid & 63, oi = tid >> 6;
    int p0 = pg*4;
    ull a0=0,a1=0,a2=0,a3=0,a4=0,a5=0;   // [kh][pair]
    const float* pt  = poolT + (size_t)c0*NPP + p0;
    const float* wsp = ws + oi*384;
    #pragma unroll 4
    for (int c = 0; c < 128; c++){
        float4 pv = *(const float4*)(pt + (size_t)c*NPP);
        ull pa0 = pk2(pv.x, pv.y), pa1 = pk2(pv.z, pv.w);
        float w0 = wsp[c], w1 = wsp[128+c], w2 = wsp[256+c];
        ull b0 = pk2(w0,w0), b1 = pk2(w1,w1), b2 = pk2(w2,w2);
        ffma2(a0, pa0, b0); ffma2(a1, pa1, b0);
        ffma2(a2, pa0, b1); ffma2(a3, pa1, b1);
        ffma2(a4, pa0, b2); ffma2(a5, pa1, b2);
    }
    size_t base = (((size_t)(cs*2 + br)*3)*OC + (o0+oi))*NPP + p0;
    *(ulonglong2*)(g_pbpart + base)            = make_ulonglong2(a0, a1);
    *(ulonglong2*)(g_pbpart + base + OC*NPP)   = make_ulonglong2(a2, a3);
    *(ulonglong2*)(g_pbpart + base + 2*OC*NPP) = make_ulonglong2(a4, a5);
}

// ---------------- prep: P2 reduce + enemy pairidx + wsum + lmid -------------
__global__ void k_prep(const int* __restrict__ x, const float* __restrict__ mcw,
                       const float* __restrict__ mlw){
    int blk = blockIdx.x;
    if (blk < 1536){
        int idx = blk*256 + threadIdx.x;           // < 2*3*OC*NPP
        int br = idx / (3*OC*NPP);
        int inner = idx % (3*OC*NPP);
        float s = g_pbpart[(0*2+br)*(3*OC*NPP) + inner]
                + g_pbpart[(1*2+br)*(3*OC*NPP) + inner]
                + g_pbpart[(2*2+br)*(3*OC*NPP) + inner]
                + g_pbpart[(3*2+br)*(3*OC*NPP) + inner];
        g_P2[idx] = s;
    } else if (blk < 1664){
        int idx = (blk - 1536)*256 + threadIdx.x;  // < HH*BB, idx = h*BB + b
        int b = idx & 255, h = idx >> 8;
        g_pi8T[idx] = (unsigned char)(x[b*LL + 2*h]*VV + x[b*LL + 2*h + 1]);
    } else if (blk < 1760){
        int idx = (blk - 1664)*256 + threadIdx.x;  // < 3*64*128
        int v = idx / 8192;
        int rem = idx % 8192;
        int base = rem*9 + 1;
        float w0 = mcw[base], w1 = mcw[base+3], w2 = mcw[base+6];
        g_Wsum[idx] = (v==0) ? (w1+w2) : (v==1) ? (w0+w1+w2) : (w0+w1);
    } else {
        int idx = (blk - 1760)*256 + threadIdx.x;  // < 64*256
        int o = idx >> 8, j = idx & 255;
        float s = 0.f;
        for (int h=1; h<127; h++) s += mlw[(size_t)(o*128 + h)*256 + j];
        g_Lmid[idx] = s;
    }
}

// ---------------- fused conv+GEMM, split-K, f32x2, double-buffered ----------
__global__ __launch_bounds__(256) void k_gemmF(int which, const float* __restrict__ W,
                                               const float* __restrict__ bias){
    extern __shared__ char dyn[];
    float (*As)[16][132]      = (float(*)[16][132])(dyn + SM_AS);
    float (*Bs)[16][128]      = (float(*)[16][128])(dyn + SM_BS);
    float (*sP2)[256]         = (float(*)[256])(dyn + SM_P2);
    unsigned char (*spi)[132] = (unsigned char(*)[132])(dyn + SM_SPI);
    float* sbias              = (float*)(dyn + SM_BIAS);

    int tid = threadIdx.x;
    int m0 = blockIdx.x * 128;
    int k0 = blockIdx.y * KC;
    int o0 = k0 >> 7;
    int lk = tid & 15, lm = tid >> 4;
    int bj = tid & 127, bk = tid >> 7;
    int tx = tid & 15, ty = tid >> 4;

    const float* P2 = g_P2 + (size_t)which*(3*OC*NPP);
    for (int e = tid; e < 1536; e += 256){
        int kh = e / 512, r = e % 512, oi = r >> 8, p = r & 255;
        sP2[kh*2 + oi][p] = P2[(size_t)kh*OC*NPP + (o0+oi)*NPP + p];
    }
    const unsigned char* piT = g_pi8T + (size_t)which*(HH*BB);
    for (int e = tid; e < 4096; e += 256){
        int h = e >> 5, g = e & 31;
        *(uchar4*)&spi[h][g*4] = *(const uchar4*)(piT + h*BB + m0 + g*4);
    }
    if (tid < 2) sbias[tid] = bias[o0 + tid];
    __syncthreads();

    ull acc[4][8];
    #pragma unroll
    for (int i=0;i<4;i++)
        #pragma unroll
        for (int j=0;j<8;j++) acc[i][j] = 0ull;

    float ra[8], rb[8];
    auto computeA = [&](int t, float* r){
        int k = k0 + t + lk;
        int h = k & 127;
        int oi = (k >> 7) - o0;
        const float* p2a = sP2[0 + oi];
        const float* p2b = sP2[2 + oi];
        const float* p2c = sP2[4 + oi];
        float vb = sbias[oi];
        bool hasA = (h > 0), hasC = (h < 127);
        #pragma unroll
        for (int i=0;i<8;i++){
            int m = lm + i*16;
            float v = vb;
            if (hasA) v += p2a[spi[h-1][m]];
            v += p2b[spi[h][m]];
            if (hasC) v += p2c[spi[h+1][m]];
            r[i] = v;
        }
    };

    computeA(0, ra);
    #pragma unroll
    for (int i=0;i<8;i++) rb[i] = W[(size_t)(k0 + bk + i*2)*NJ + bj];
    #pragma unroll
    for (int i=0;i<8;i++) As[0][lk][lm + i*16] = ra[i];
    #pragma unroll
    for (int i=0;i<8;i++) Bs[0][bk + i*2][bj] = rb[i];
    __syncthreads();

    int buf = 0;
    for (int t = 16; t < KC; t += 16){
        computeA(t, ra);
        #pragma unroll
        for (int i=0;i<8;i++) rb[i] = W[(size_t)(k0 + t + bk + i*2)*NJ + bj];
        #pragma unroll
        for (int kk=0; kk<16; kk++){
            ulonglong2 a01 = *(const ulonglong2*)&As[buf][kk][ty*8];
            ulonglong2 a23 = *(const ulonglong2*)&As[buf][kk][ty*8 + 4];
            float4 b0 = *(const float4*)&Bs[buf][kk][tx*4];
            float4 b1 = *(const float4*)&Bs[buf][kk][64 + tx*4];
            ull ap[4] = { a01.x, a01.y, a23.x, a23.y };
            ull bd[8] = { pk2(b0.x,b0.x), pk2(b0.y,b0.y),
                          pk2(b0.z,b0.z), pk2(b0.w,b0.w),
                          pk2(b1.x,b1.x), pk2(b1.y,b1.y),
                          pk2(b1.z,b1.z), pk2(b1.w,b1.w) };
            #pragma unroll
            for (int i=0;i<4;i++)
                #pragma unroll
                for (int j=0;j<8;j++)
                    ffma2(acc[i][j], ap[i], bd[j]);
        }
        #pragma unroll
        for (int i=0;i<8;i++) As[buf^1][lk][lm + i*16] = ra[i];
        #pragma unroll
        for (int i=0;i<8;i++) Bs[buf^1][bk + i*2][bj] = rb[i];
        __syncthreads();
        buf ^= 1;
    }
    #pragma unroll
    for (int kk=0; kk<16; kk++){
        ulonglong2 a01 = *(const ulonglong2*)&As[buf][kk][ty*8];
        ulonglong2 a23 = *(const ulonglong2*)&As[buf][kk][ty*8 + 4];
        float4 b0 = *(const float4*)&Bs[buf][kk][tx*4];
        float4 b1 = *(const float4*)&Bs[buf][kk][64 + tx*4];
        ull ap[4] = { a01.x, a01.y, a23.x, a23.y };
        ull bd[8] = { pk2(b0.x,b0.x), pk2(b0.y,b0.y),
                      pk2(b0.z,b0.z), pk2(b0.w,b0.w),
                      pk2(b1.x,b1.x), pk2(b1.y,b1.y),
                      pk2(b1.z,b1.z), pk2(b1.w,b1.w) };
        #pragma unroll
        for (int i=0;i<4;i++)
            #pragma unroll
            for (int j=0;j<8;j++)
                ffma2(acc[i][j], ap[i], bd[j]);
    }

    float* outp = g_partial + (size_t)blockIdx.y * (BB*NJ);
    #pragma unroll
    for (int i=0;i<4;i++){
        int mlo = m0 + ty*8 + 2*i;
        float rlo[8], rhi[8];
        #pragma unroll
        for (int j=0;j<8;j++) upk2(acc[i][j], rlo[j], rhi[j]);
        *(float4*)&outp[(size_t)mlo*NJ + tx*4]          = make_float4(rlo[0],rlo[1],rlo[2],rlo[3]);
        *(float4*)&outp[(size_t)mlo*NJ + 64 + tx*4]     = make_float4(rlo[4],rlo[5],rlo[6],rlo[7]);
        *(float4*)&outp[(size_t)(mlo+1)*NJ + tx*4]      = make_float4(rhi[0],rhi[1],rhi[2],rhi[3]);
        *(float4*)&outp[(size_t)(mlo+1)*NJ + 64 + tx*4] = make_float4(rhi[4],rhi[5],rhi[6],rhi[7]);
    }
}

// ---------------- mid: reduce + softmax + manip conv + lin + tokens + pair --
// one block per batch row b; everything b-local stays in smem
__global__ __launch_bounds__(256) void k_mid(const float* __restrict__ bias,
                                             const float* __restrict__ mcb,
                                             const float* __restrict__ mlw,
                                             const float* __restrict__ mlb){
    __shared__ float red[128];
    __shared__ float eo[128];
    __shared__ float rr[192];
    __shared__ unsigned char stok[256];
    int b = blockIdx.x, t = threadIdx.x;
    float v = 0.f;
    if (t < 128){
        float s = bias[t];
        #pragma unroll 8
        for (int kz=0; kz<SPLITK; kz++) s += g_partial[(size_t)(kz*BB + b)*NJ + t];
        v = s;
        red[t] = v;
    }
    __syncthreads();
    for (int st=64; st; st>>=1){ if (t < st) red[t] = fmaxf(red[t], red[t+st]); __syncthreads(); }
    float mx = red[0]; __syncthreads();
    float e = 0.f;
    if (t < 128){ e = expf(v - mx); red[t] = e; }
    __syncthreads();
    for (int st=64; st; st>>=1){ if (t < st) red[t] += red[t+st]; __syncthreads(); }
    if (t < 128) eo[t] = e / red[0];
    __syncthreads();
    // manipulator conv (collapsed): 192 outputs
    if (t < 192){
        int vv = t >> 6, o = t & 63;
        const float* ws = g_Wsum + vv*8192 + o*128;
        float acc = mcb[o];
        for (int c=0;c<128;c++) acc = fmaf(eo[c], ws[c], acc);
        rr[vv*64 + o] = fmaxf(acc, 0.f);
    }
    __syncthreads();
    // manip linear -> tokens (j = t, 256 threads)
    {
        int j = t;
        float s = mlb[j];
        for (int o=0; o<64; o++){
            s = fmaf(rr[o],       mlw[(size_t)o*32768 + j],          s);
            s = fmaf(rr[64 + o],  g_Lmid[o*256 + j],                 s);
            s = fmaf(rr[128 + o], mlw[(size_t)o*32768 + 32512 + j],  s);
        }
        int tk = (int)floorf(fabsf(s) * 100.0f);
        stok[j] = (unsigned char)(tk % VV);
    }
    __syncthreads();
    if (t < 128)
        g_pi8T[HH*BB + t*BB + b] = (unsigned char)(stok[2*t]*VV + stok[2*t+1]);
}

// ---------------- friend: reduce + final linear + softmax -------------------
__global__ void k_redlin2(const float* __restrict__ bias, const float* __restrict__ w2,
                          const float* __restrict__ b2, float* __restrict__ out){
    __shared__ float f[128];
    int b = blockIdx.x, t = threadIdx.x;
    float s = bias[t];
    #pragma unroll 8
    for (int kz=0; kz<SPLITK; kz++) s += g_partial[(size_t)(kz*BB + b)*NJ + t];
    f[t] = s; __syncthreads();
    if (t < 32){
        float logit = -INFINITY;
        if (t < VV){
            logit = b2[t];
            for (int j=0; j<128; j++) logit = fmaf(f[j], w2[j*VV + t], logit);
        }
        float mx = logit;
        for (int off=16; off; off>>=1) mx = fmaxf(mx, __shfl_xor_sync(0xffffffffu, mx, off));
        float e = (t < VV) ? expf(logit - mx) : 0.f;
        float sm = e;
        for (int off=16; off; off>>=1) sm += __shfl_xor_sync(0xffffffffu, sm, off);
        if (t < VV) out[b*VV + t] = e / sm;
    }
}

// ---------------- launch ----------------------------------------------------
extern "C" void kernel_launch(void* const* d_in, const int* in_sizes, int n_in,
                              void* d_out, int out_size){
    const int*   x    = (const int*)  d_in[0];
    const float* eemb = (const float*)d_in[1];
    const float* ecw  = (const float*)d_in[2];
    const float* ecb  = (const float*)d_in[3];
    const float* elw  = (const float*)d_in[4];
    const float* elb  = (const float*)d_in[5];
    // d_in[6] rand_proj: dead (fog_of_war == identity permutation)
    const float* mcw  = (const float*)d_in[7];
    const float* mcb  = (const float*)d_in[8];
    const float* mlw  = (const float*)d_in[9];
    const float* mlb  = (const float*)d_in[10];
    const float* femb = (const float*)d_in[11];
    const float* fcw  = (const float*)d_in[12];
    const float* fcb  = (const float*)d_in[13];
    const float* flw1 = (const float*)d_in[14];
    const float* flb1 = (const float*)d_in[15];
    const float* flw2 = (const float*)d_in[16];
    const float* flb2 = (const float*)d_in[17];
    float* out = (float*)d_out;

    cudaFuncSetAttribute(k_gemmF, cudaFuncAttributeMaxDynamicSharedMemorySize, SM_TOTAL);

    k_poolT2<<<(2*EMBD*NPP)/256, 256>>>(eemb, femb);           // 1
    k_pbuild2<<<dim3(32,4,2), 512>>>(ecw, fcw);                // 2
    k_prep<<<1824, 256>>>(x, mcw, mlw);                        // 3

    k_gemmF<<<dim3(2, SPLITK), 256, SM_TOTAL>>>(0, elw, ecb);  // 4 <- profiled
    k_mid<<<BB, 256>>>(elb, mcb, mlw, mlb);                    // 5

    k_gemmF<<<dim3(2, SPLITK), 256, SM_TOTAL>>>(1, flw1, fcb); // 6
    k_redlin2<<<BB, 128>>>(flb1, flw2, flb2, out);             // 7
}